// round 11
// baseline (speedup 1.0000x reference)
#include <cuda_runtime.h>
#include <cuda_bf16.h>
#include <cstdint>

// ---------------------------------------------------------------------------
// Fused edge-MLP, persistent CTAs, tcgen05, weights as TMEM A-operand,
// COLUMN-GROUP PIPELINED MMA (two N=64 groups per chain, per-group commits).
//   D1[f,e] = sum_k W1[k,f]*pair[e,k]; H = relu(D1+b1) -> SMEM
//   D2[g,e] = sum_f W2[f,g]*H[e,f];   out = relu(D2+b2).W3 + b3
// 3-term bf16 split = fp32-class accuracy.
// TMEM: W1h 0-127 | W1l 128-255 | W2h 256-319 | W2l 320-383 | D 384-511.
// Per tile: epi1(group-streamed) ∥ gather(t+1) -> chain2 g0,g1 ->
// drain g0 -> issue chain1(t+1) g0 -> drain g1 -> issue g1 -> fold/store.
// ---------------------------------------------------------------------------

#if defined(__CUDA_ARCH__) && defined(__CUDA_ARCH_FEAT_SM103_ALL)
#define EDGE_USE_TC 1
#else
#define EDGE_USE_TC 0
#endif

#define NT      512
#define TILE_M  128
#define GRID    148

// idesc kind::f16: F32 accum, BF16 a/b, M=128; N variants
#define IDESC64  0x8100490u   // N=64

// tc-path SMEM byte offsets
#define SMEM_PH      0         // pair hi: 4 blocks x 16KB ([128e x 64k] SW128)
#define SMEM_PL      65536     // pair lo
#define SMEM_HH      131072    // H hi: 2 blocks x 16KB
#define SMEM_HL      163840    // H lo
#define SMEM_RED     196608    // 4 x 128 fp32 partials
#define SMEM_TMEMPTR 198656
#define SMEM_C1B     198664    // chain1 group barriers (2 x 8B)
#define SMEM_C2B     198680    // chain2 group barriers
#define SMEM_DB      198696    // drain-done barriers (count 8)
#define SMEM_TOTAL   198720

// Prepared weights, transposed+packed for TMEM A-operand:
// word(m, c) = bf16(W[2c, m]) | bf16(W[2c+1, m])<<16  (hi and lo splits)
__device__ __align__(16) uint32_t g_W1t_h[16384];   // [m=128][c=128]
__device__ __align__(16) uint32_t g_W1t_l[16384];
__device__ __align__(16) uint32_t g_W2t_h[8192];    // [m=128][c=64]
__device__ __align__(16) uint32_t g_W2t_l[8192];

__device__ __forceinline__ int sw128(int off) { return off ^ ((off >> 3) & 0x70); }

#if EDGE_USE_TC

__device__ __forceinline__ uint32_t smem_u32_of(const void* p) {
    uint32_t a;
    asm("{ .reg .u64 t; cvta.to.shared.u64 t, %1; cvt.u32.u64 %0, t; }"
        : "=r"(a) : "l"(p));
    return a;
}
__device__ __forceinline__ uint32_t elect_one() {
    uint32_t pred;
    asm volatile("{ .reg .pred p; elect.sync _|p, 0xFFFFFFFF; selp.b32 %0, 1, 0, p; }"
                 : "=r"(pred));
    return pred;
}
__device__ __forceinline__ uint64_t smem_desc(uint32_t addr) {
    // SW128, Blackwell version=1, SBO=64, LBO=1 (K-major)
    return 0x4000404000010000ULL | ((uint64_t)(addr >> 4) & 0x3FFF);
}
__device__ __forceinline__ void mma_f16_ts64(uint32_t d_tmem, uint32_t a_tmem,
                                             uint64_t b_desc, uint32_t en) {
    asm volatile(
        "{\n\t.reg .pred p;\n\tsetp.ne.u32 p, %4, 0;\n\t"
        "tcgen05.mma.cta_group::1.kind::f16 [%0], [%1], %2, %3, {%5,%5,%5,%5}, p;\n\t}"
        :: "r"(d_tmem), "r"(a_tmem), "l"(b_desc), "r"(IDESC64), "r"(en), "r"(0u)
        : "memory");
}

#define TCGEN05_ALLOC(sa, n) \
    asm volatile("tcgen05.alloc.cta_group::1.sync.aligned.shared::cta.b32 [%0], %1;" \
                 :: "r"((uint32_t)(sa)), "r"((uint32_t)(n)) : "memory")
#define TCGEN05_DEALLOC(t, n) \
    asm volatile("tcgen05.dealloc.cta_group::1.sync.aligned.b32 %0, %1;" \
                 :: "r"(t), "r"((uint32_t)(n)))
#define TCGEN05_COMMIT(mb) \
    asm volatile("tcgen05.commit.cta_group::1.mbarrier::arrive::one.shared::cluster.b64 [%0];" \
                 :: "r"((uint32_t)(mb)) : "memory")
#define TCGEN05_WAIT_LD()  asm volatile("tcgen05.wait::ld.sync.aligned;" ::: "memory")
#define TCGEN05_WAIT_ST()  asm volatile("tcgen05.wait::st.sync.aligned;" ::: "memory")
#define TCGEN05_FENCE_BEFORE() asm volatile("tcgen05.fence::before_thread_sync;" ::: "memory")
#define TCGEN05_FENCE_AFTER()  asm volatile("tcgen05.fence::after_thread_sync;" ::: "memory")
#define FENCE_ASYNC() asm volatile("fence.proxy.async.shared::cta;" ::: "memory")
#define MBARRIER_INIT(mb, c) \
    asm volatile("mbarrier.init.shared.b64 [%0], %1;" :: "r"((uint32_t)(mb)), "r"((uint32_t)(c)) : "memory")
#define MBARRIER_INVAL(mb) \
    asm volatile("mbarrier.inval.shared.b64 [%0];" :: "r"((uint32_t)(mb)) : "memory")
#define MBARRIER_ARRIVE(mb) \
    asm volatile("mbarrier.arrive.shared.b64 _, [%0];" :: "r"((uint32_t)(mb)) : "memory")

#define MBARRIER_WAIT_PARITY(mb, ph) do {                                          \
    uint32_t _m = (uint32_t)(mb), _p = (uint32_t)(ph), _done;                      \
    asm volatile("{\n\t.reg .pred p;\n\t"                                          \
        "mbarrier.try_wait.parity.acquire.cta.shared::cta.b64 p, [%1], %2;\n\t"    \
        "selp.b32 %0, 1, 0, p;\n\t}" : "=r"(_done) : "r"(_m), "r"(_p) : "memory"); \
    if (!_done) {                                                                  \
        asm volatile("{\n\t.reg .pred P1;\n\t"                                     \
        "WL_%=:\n\t"                                                               \
        "mbarrier.try_wait.parity.acquire.cta.shared::cta.b64 P1, [%0], %1, 0x989680;\n\t" \
        "@P1 bra.uni WD_%=;\n\t"                                                   \
        "bra.uni WL_%=;\n\t"                                                       \
        "WD_%=:\n\t}" :: "r"(_m), "r"(_p) : "memory");                             \
    }                                                                              \
} while (0)

#define LDTM_X32(r, a)                                                             \
    asm volatile("tcgen05.ld.sync.aligned.32x32b.x32.b32 "                         \
        "{%0,%1,%2,%3,%4,%5,%6,%7,%8,%9,%10,%11,%12,%13,%14,%15,"                  \
        "%16,%17,%18,%19,%20,%21,%22,%23,%24,%25,%26,%27,%28,%29,%30,%31}, [%32];" \
        : "=r"((r)[0]),"=r"((r)[1]),"=r"((r)[2]),"=r"((r)[3]),                     \
          "=r"((r)[4]),"=r"((r)[5]),"=r"((r)[6]),"=r"((r)[7]),                     \
          "=r"((r)[8]),"=r"((r)[9]),"=r"((r)[10]),"=r"((r)[11]),                   \
          "=r"((r)[12]),"=r"((r)[13]),"=r"((r)[14]),"=r"((r)[15]),                 \
          "=r"((r)[16]),"=r"((r)[17]),"=r"((r)[18]),"=r"((r)[19]),                 \
          "=r"((r)[20]),"=r"((r)[21]),"=r"((r)[22]),"=r"((r)[23]),                 \
          "=r"((r)[24]),"=r"((r)[25]),"=r"((r)[26]),"=r"((r)[27]),                 \
          "=r"((r)[28]),"=r"((r)[29]),"=r"((r)[30]),"=r"((r)[31])                  \
        : "r"(a))

#define STTM_X32(a, r)                                                             \
    asm volatile("tcgen05.st.sync.aligned.32x32b.x32.b32 [%0], "                   \
        "{%1,%2,%3,%4,%5,%6,%7,%8,%9,%10,%11,%12,%13,%14,%15,%16,"                 \
        "%17,%18,%19,%20,%21,%22,%23,%24,%25,%26,%27,%28,%29,%30,%31,%32};"        \
        :: "r"(a),                                                                 \
           "r"((r)[0]),"r"((r)[1]),"r"((r)[2]),"r"((r)[3]),                        \
           "r"((r)[4]),"r"((r)[5]),"r"((r)[6]),"r"((r)[7]),                        \
           "r"((r)[8]),"r"((r)[9]),"r"((r)[10]),"r"((r)[11]),                      \
           "r"((r)[12]),"r"((r)[13]),"r"((r)[14]),"r"((r)[15]),                    \
           "r"((r)[16]),"r"((r)[17]),"r"((r)[18]),"r"((r)[19]),                    \
           "r"((r)[20]),"r"((r)[21]),"r"((r)[22]),"r"((r)[23]),                    \
           "r"((r)[24]),"r"((r)[25]),"r"((r)[26]),"r"((r)[27]),                    \
           "r"((r)[28]),"r"((r)[29]),"r"((r)[30]),"r"((r)[31])                     \
        : "memory")

__device__ __forceinline__ uint32_t pack_bf2f(float a, float b) {
    __nv_bfloat162 t = __floats2bfloat162_rn(a, b);   // .x = low half
    return *reinterpret_cast<uint32_t*>(&t);
}
__device__ __forceinline__ uint32_t pack_bf2(__nv_bfloat16 a, __nv_bfloat16 b) {
    __nv_bfloat162 t;
    t.x = a; t.y = b;
    return *reinterpret_cast<uint32_t*>(&t);
}

#endif  // EDGE_USE_TC

// ------------------------------ prep kernel -------------------------------
__global__ void prep_kernel(const float* __restrict__ W1,
                            const float* __restrict__ W2) {
    int i = blockIdx.x * blockDim.x + threadIdx.x;
    if (i < 16384) {                 // W1: m = out-feat, c = k-pair (128)
        int m = i >> 7, c = i & 127;
        float a = W1[(2 * c) * 128 + m];
        float b = W1[(2 * c + 1) * 128 + m];
        __nv_bfloat16 ah = __float2bfloat16_rn(a), bh = __float2bfloat16_rn(b);
        float al = a - __bfloat162float(ah), bl = b - __bfloat162float(bh);
        __nv_bfloat162 hi; hi.x = ah; hi.y = bh;
        __nv_bfloat162 lo = __floats2bfloat162_rn(al, bl);
        g_W1t_h[i] = *reinterpret_cast<uint32_t*>(&hi);
        g_W1t_l[i] = *reinterpret_cast<uint32_t*>(&lo);
    } else if (i < 24576) {          // W2: c = k-pair (64)
        int j = i - 16384;
        int m = j >> 6, c = j & 63;
        float a = W2[(2 * c) * 128 + m];
        float b = W2[(2 * c + 1) * 128 + m];
        __nv_bfloat16 ah = __float2bfloat16_rn(a), bh = __float2bfloat16_rn(b);
        float al = a - __bfloat162float(ah), bl = b - __bfloat162float(bh);
        __nv_bfloat162 hi; hi.x = ah; hi.y = bh;
        __nv_bfloat162 lo = __floats2bfloat162_rn(al, bl);
        g_W2t_h[j] = *reinterpret_cast<uint32_t*>(&hi);
        g_W2t_l[j] = *reinterpret_cast<uint32_t*>(&lo);
    }
}

// ------------------------------ main kernel -------------------------------

__global__ __launch_bounds__(NT, 1)
void edge_mlp_kernel(const float* __restrict__ x1,
                     const float* __restrict__ x2,
                     const int* __restrict__ ei,
                     const float* __restrict__ b1g,
                     const float* __restrict__ b2g,
                     const float* __restrict__ W3g,
                     const float* __restrict__ b3g,
                     float* __restrict__ out, int E) {
    const int ntiles = (E + TILE_M - 1) / TILE_M;

#if EDGE_USE_TC
    extern __shared__ char smem[];
    const uint32_t sb = smem_u32_of(smem);
    const int tid  = threadIdx.x;
    const int lane = tid & 31;
    const int wid  = tid >> 5;                // 0..15
    const int sp   = wid & 3;                 // TMEM subpartition
    const int cc   = wid >> 2;                // drain chunk (0..3)
    const uint32_t rowbits = (uint32_t)sp << 21;
    const int g    = sp * 32 + lane;          // this lane's feature row

    if (wid == 0) TCGEN05_ALLOC(sb + SMEM_TMEMPTR, 512);
    if (tid == 0) {
        MBARRIER_INIT(sb + SMEM_C1B,     1); MBARRIER_INIT(sb + SMEM_C1B + 8, 1);
        MBARRIER_INIT(sb + SMEM_C2B,     1); MBARRIER_INIT(sb + SMEM_C2B + 8, 1);
        MBARRIER_INIT(sb + SMEM_DB,      8); MBARRIER_INIT(sb + SMEM_DB  + 8, 8);
    }
    __syncthreads();
    uint32_t tmem;
    asm volatile("ld.shared.b32 %0, [%1];" : "=r"(tmem) : "r"(sb + SMEM_TMEMPTR));
    const uint32_t tD = tmem + 384;

    // ---- one-time: upload weights to TMEM (warps 0-3: W1, 4-7: W2) ----
    {
        uint32_t ww[32];
        if (wid < 4) {
#pragma unroll
            for (int q = 0; q < 4; ++q) {
#pragma unroll
                for (int i = 0; i < 32; ++i) ww[i] = g_W1t_h[g * 128 + 32 * q + i];
                STTM_X32(tmem + 32 * q + rowbits, ww);
            }
#pragma unroll
            for (int q = 0; q < 4; ++q) {
#pragma unroll
                for (int i = 0; i < 32; ++i) ww[i] = g_W1t_l[g * 128 + 32 * q + i];
                STTM_X32(tmem + 128 + 32 * q + rowbits, ww);
            }
            TCGEN05_WAIT_ST();
        } else if (wid < 8) {
#pragma unroll
            for (int q = 0; q < 2; ++q) {
#pragma unroll
                for (int i = 0; i < 32; ++i) ww[i] = g_W2t_h[g * 64 + 32 * q + i];
                STTM_X32(tmem + 256 + 32 * q + rowbits, ww);
            }
#pragma unroll
            for (int q = 0; q < 2; ++q) {
#pragma unroll
                for (int i = 0; i < 32; ++i) ww[i] = g_W2t_l[g * 64 + 32 * q + i];
                STTM_X32(tmem + 320 + 32 * q + rowbits, ww);
            }
            TCGEN05_WAIT_ST();
        }
    }
    TCGEN05_FENCE_BEFORE();
    __syncthreads();

    // per-lane constants
    const float b1v = b1g[g];
    const float b2v = b2g[g];
    const float w3v = W3g[g];
    const float b3v = b3g[0];
    const int hchunk = g >> 6;
    const int hcolb  = (g & 63) * 2;

    // ---- gather (warps 8-15): coalesced indices + shfl, batched rows ----
    auto gather8 = [&](int tt) {
        const int gw    = wid & 7;
        const int half  = gw >> 2;
        const int mbase = (gw & 3) * 32;
        const int coff  = 8 * (lane & 15);
        const int csel  = lane >> 4;
        const int chunk = half * 2 + csel;
        const float* xbase = half ? x2 : x1;

        int e_lane = tt * TILE_M + mbase + lane;
        int node_lane = -1;
        if (e_lane < E) node_lane = ei[(long long)half * E + e_lane];

#pragma unroll
        for (int b = 0; b < 4; ++b) {
            int nodes[8];
#pragma unroll
            for (int i = 0; i < 8; ++i)
                nodes[i] = __shfl_sync(0xffffffffu, node_lane, b * 8 + i);
            float4 v[8];
#pragma unroll
            for (int i = 0; i < 8; ++i)
                v[i] = (nodes[i] >= 0)
                     ? reinterpret_cast<const float4*>(xbase + (long long)nodes[i] * 128)[lane]
                     : make_float4(0.f, 0.f, 0.f, 0.f);
#pragma unroll
            for (int i = 0; i < 8; ++i) {
                int m = mbase + b * 8 + i;
                __nv_bfloat162 h0 = __floats2bfloat162_rn(v[i].x, v[i].y);
                __nv_bfloat162 h1 = __floats2bfloat162_rn(v[i].z, v[i].w);
                uint2 hh = make_uint2(*reinterpret_cast<uint32_t*>(&h0),
                                      *reinterpret_cast<uint32_t*>(&h1));
                uint2 ll = make_uint2(pack_bf2f(v[i].x - __bfloat162float(h0.x),
                                                v[i].y - __bfloat162float(h0.y)),
                                      pack_bf2f(v[i].z - __bfloat162float(h1.x),
                                                v[i].w - __bfloat162float(h1.y)));
                int off = chunk * 16384 + sw128(m * 128 + coff);
                *reinterpret_cast<uint2*>(smem + SMEM_PH + off) = hh;
                *reinterpret_cast<uint2*>(smem + SMEM_PL + off) = ll;
            }
        }
        FENCE_ASYNC();
    };

    // ---- group-wise MMA issue (N=64 col groups) ----
    auto issue_chain1_g = [&](int gg) {
        TCGEN05_FENCE_AFTER();
        const uint32_t dcol = tD + 64u * (uint32_t)gg;
        const uint64_t boff = 512u * (uint32_t)gg;   // 64 edge-rows x 128B /16
#pragma unroll
        for (int pass = 0; pass < 3; ++pass) {
            const uint32_t acol = (pass == 2) ? 128u : 0u;          // W1l : W1h
            const uint32_t bbase = (pass == 1) ? SMEM_PL : SMEM_PH;
            for (int c = 0; c < 4; ++c) {
                uint64_t bd = smem_desc(sb + bbase + c * 16384) + boff;
                for (int k = 0; k < 4; ++k)
                    mma_f16_ts64(dcol, tmem + acol + (c * 4 + k) * 8, bd + k * 2,
                                 (pass == 0 && c == 0 && k == 0) ? 0u : 1u);
            }
        }
        TCGEN05_COMMIT(sb + SMEM_C1B + 8 * gg);
    };
    auto issue_chain2_g = [&](int gg) {
        TCGEN05_FENCE_AFTER();
        const uint32_t dcol = tD + 64u * (uint32_t)gg;
        const uint64_t boff = 512u * (uint32_t)gg;
#pragma unroll
        for (int pass = 0; pass < 3; ++pass) {
            const uint32_t acol = (pass == 2) ? 320u : 256u;        // W2l : W2h
            const uint32_t bbase = (pass == 1) ? SMEM_HL : SMEM_HH;
            for (int c = 0; c < 2; ++c) {
                uint64_t bd = smem_desc(sb + bbase + c * 16384) + boff;
                for (int k = 0; k < 4; ++k)
                    mma_f16_ts64(dcol, tmem + acol + (c * 4 + k) * 8, bd + k * 2,
                                 (pass == 0 && c == 0 && k == 0) ? 0u : 1u);
            }
        }
        TCGEN05_COMMIT(sb + SMEM_C2B + 8 * gg);
    };

    // ---- prologue ----
    int t = blockIdx.x;
    int q = 0;
    if (t < ntiles) {
        if (wid >= 8) gather8(t);
        __syncthreads();
        if (wid == 4 && elect_one()) { issue_chain1_g(0); issue_chain1_g(1); }
    }

    for (; t < ntiles; t += GRID) {
        const bool more = (t + GRID < ntiles);

        // -------- epi1 (warps 0-7, group-streamed) ∥ gather(t+GRID) --------
        if (wid < 8) {
            const int grp = wid >> 2;          // 0: chunks 0,1 | 1: chunks 2,3
            MBARRIER_WAIT_PARITY(sb + SMEM_C1B + 8 * grp, q);
            TCGEN05_FENCE_AFTER();
            const int ccb = grp * 2;
#pragma unroll
            for (int qq = 0; qq < 2; ++qq) {
                const int cce = ccb + qq;
                uint32_t d[32];
                LDTM_X32(d, tD + 32 * cce);
                TCGEN05_WAIT_LD();
#pragma unroll
                for (int j = 0; j < 32; ++j) {
                    float v  = fmaxf(__uint_as_float(d[j]) + b1v, 0.0f);
                    float vo = __shfl_xor_sync(0xffffffffu, v, 1);
                    __nv_bfloat16 hs = __float2bfloat16_rn(v);
                    __nv_bfloat16 ho = __float2bfloat16_rn(vo);
                    float ls = v - __bfloat162float(hs);
                    float lo = vo - __bfloat162float(ho);
                    if (!(lane & 1)) {
                        int e = cce * 32 + j;
                        int off = hchunk * 16384 + sw128(e * 128 + hcolb);
                        *reinterpret_cast<uint32_t*>(smem + SMEM_HH + off) =
                            pack_bf2(hs, ho);
                        *reinterpret_cast<uint32_t*>(smem + SMEM_HL + off) =
                            pack_bf2f(ls, lo);
                    }
                }
            }
            FENCE_ASYNC();
        } else {
            // gather must not overwrite P until chain-1 fully done (group 1 last)
            MBARRIER_WAIT_PARITY(sb + SMEM_C1B + 8, q);
            if (more) gather8(t + GRID);
        }
        __syncthreads();                       // S1: H + P(t+GRID) visible

        // -------- chain-2 (grouped commits) --------------------------------
        if (wid == 4 && elect_one()) { issue_chain2_g(0); issue_chain2_g(1); }

        // -------- drain D2 per group; signal drain-done --------------------
        const int grp2 = cc >> 1;
        MBARRIER_WAIT_PARITY(sb + SMEM_C2B + 8 * grp2, q);
        TCGEN05_FENCE_AFTER();
        uint32_t d2[32];
        LDTM_X32(d2, tD + 32 * cc);
        TCGEN05_WAIT_LD();
        if (elect_one()) MBARRIER_ARRIVE(sb + SMEM_DB + 8 * grp2);

        // -------- issue chain-1(t+GRID) group-by-group as D frees ----------
        if (more && wid == 4 && elect_one()) {
            MBARRIER_WAIT_PARITY(sb + SMEM_DB, q);
            issue_chain1_g(0);
            MBARRIER_WAIT_PARITY(sb + SMEM_DB + 8, q);
            issue_chain1_g(1);
        }

        // -------- fold-reduce + out store (overlaps chain-1) ---------------
        {
            float v[32];
#pragma unroll
            for (int j = 0; j < 32; ++j)
                v[j] = fmaxf(__uint_as_float(d2[j]) + b2v, 0.0f) * w3v;
#pragma unroll
            for (int m = 16; m > 0; m >>= 1) {
#pragma unroll
                for (int j = 0; j < m; ++j) {
                    float x = (lane & m) ? v[j] : v[j + m];
                    float y = __shfl_xor_sync(0xffffffffu, x, m);
                    v[j] = ((lane & m) ? v[j + m] : v[j]) + y;
                }
            }
            ((float*)(smem + SMEM_RED))[sp * 128 + cc * 32 + lane] = v[0];
        }
        __syncthreads();                       // S2: partials visible
        if (tid < TILE_M) {
            int e = t * TILE_M + tid;
            if (e < E) {
                const float* red = (const float*)(smem + SMEM_RED);
                out[e] = red[tid] + red[128 + tid] + red[256 + tid] +
                         red[384 + tid] + b3v;
            }
        }
        q ^= 1;
    }

    __syncthreads();
    if (tid == 0) {
        MBARRIER_INVAL(sb + SMEM_C1B); MBARRIER_INVAL(sb + SMEM_C1B + 8);
        MBARRIER_INVAL(sb + SMEM_C2B); MBARRIER_INVAL(sb + SMEM_C2B + 8);
        MBARRIER_INVAL(sb + SMEM_DB);  MBARRIER_INVAL(sb + SMEM_DB + 8);
    }
    __syncthreads();
    if (wid == 0) TCGEN05_DEALLOC(tmem, 512);

#else
    // unreachable on GB300 (sm_103a cubin preferred); minimal defined body
    (void)x1; (void)x2; (void)ei; (void)b1g; (void)b2g; (void)W3g;
    int stride = gridDim.x * blockDim.x;
    for (int e = blockIdx.x * blockDim.x + threadIdx.x; e < E; e += stride)
        out[e] = b3g[0];
    (void)ntiles;
#endif
}

// Full-precision standalone fallback (launched only if tc kernel unavailable).
__global__ __launch_bounds__(256, 1)
void edge_mlp_ref_kernel(const float* __restrict__ x1,
                         const float* __restrict__ x2,
                         const int* __restrict__ ei,
                         const float* __restrict__ W1, const float* __restrict__ b1,
                         const float* __restrict__ W2, const float* __restrict__ b2,
                         const float* __restrict__ W3, const float* __restrict__ b3,
                         float* __restrict__ out, int E) {
    int stride = gridDim.x * blockDim.x;
    for (int e = blockIdx.x * blockDim.x + threadIdx.x; e < E; e += stride) {
        const float* xs = x1 + (long long)ei[e] * 128;
        const float* xt = x2 + (long long)ei[E + e] * 128;
        float h1[128], h2[128];
        for (int f = 0; f < 128; ++f) {
            float a = b1[f];
            for (int k = 0; k < 128; ++k) a += xs[k] * W1[k * 128 + f];
            for (int k = 0; k < 128; ++k) a += xt[k] * W1[(128 + k) * 128 + f];
            h1[f] = fmaxf(a, 0.0f);
        }
        for (int g2 = 0; g2 < 128; ++g2) {
            float a = b2[g2];
            for (int f = 0; f < 128; ++f) a += h1[f] * W2[f * 128 + g2];
            h2[g2] = fmaxf(a, 0.0f);
        }
        float acc = b3[0];
        for (int g2 = 0; g2 < 128; ++g2) acc += h2[g2] * W3[g2];
        out[e] = acc;
    }
}

extern "C" void kernel_launch(void* const* d_in, const int* in_sizes, int n_in,
                              void* d_out, int out_size) {
    const float* x1 = (const float*)d_in[0];
    const float* x2 = (const float*)d_in[1];
    const int*   ei = (const int*)d_in[2];
    const float* W1 = (const float*)d_in[3];
    const float* b1 = (const float*)d_in[4];
    const float* W2 = (const float*)d_in[5];
    const float* b2 = (const float*)d_in[6];
    const float* W3 = (const float*)d_in[7];
    const float* b3 = (const float*)d_in[8];
    float*       out = (float*)d_out;

    int E = in_sizes[2] / 2;

    static int use_tc = -1;
    if (use_tc < 0) {
        cudaFuncAttributes attr;
        cudaError_t err = cudaFuncGetAttributes(&attr, edge_mlp_kernel);
        use_tc = (err == cudaSuccess && attr.maxThreadsPerBlock >= NT) ? 1 : 0;
        if (use_tc) {
            if (cudaFuncSetAttribute(edge_mlp_kernel,
                                     cudaFuncAttributeMaxDynamicSharedMemorySize,
                                     SMEM_TOTAL) != cudaSuccess)
                use_tc = 0;
        }
        cudaGetLastError();  // clear probe state
    }

    if (use_tc) {
        prep_kernel<<<96, 256>>>(W1, W2);
        edge_mlp_kernel<<<GRID, NT, SMEM_TOTAL>>>(x1, x2, ei, b1, b2, W3, b3,
                                                  out, E);
    } else {
        edge_mlp_ref_kernel<<<GRID, 256>>>(x1, x2, ei, W1, b1, W2, b2, W3, b3,
                                           out, E);
    }
}

// round 12
// speedup vs baseline: 1.6157x; 1.6157x over previous
#include <cuda_runtime.h>
#include <cuda_bf16.h>
#include <cstdint>

// ---------------------------------------------------------------------------
// Fused edge-MLP, restructured algebraically:
//   y1 = x1 @ W1[:128]   (per NODE, 100K rows)   -- node_kernel
//   y2 = x2 @ W1[128:]   (per NODE)
//   per edge: h = relu(y1[src] + y2[dst] + b1)   -- edge_kernel (gather=combine)
//             D2[g,e] = sum_f W2[f,g] * h[e,f]   (tcgen05, W2^T in TMEM)
//             out = relu(D2+b2).W3 + b3
// 3-term bf16 split everywhere = fp32-class accuracy.
// Edge kernel TMEM: W2h 0-63 | W2l 64-127 | D0 128-255 | D1 256-383.
// Double-buffered H (SMEM) + D (TMEM): chain2(t) overlaps gather(t+1).
// ---------------------------------------------------------------------------

#if defined(__CUDA_ARCH__) && defined(__CUDA_ARCH_FEAT_SM103_ALL)
#define EDGE_USE_TC 1
#else
#define EDGE_USE_TC 0
#endif

#define NT      512
#define TILE_M  128
#define GRID    148
#define MAXN    100096

// idesc kind::f16: F32 accum, BF16 a/b, N=128, M=128
#define IDESC   0x8200490u

// node kernel SMEM
#define A_PH      0
#define A_PL      32768
#define A_TMEMPTR 65536
#define A_BAR     65544
#define A_TOTAL   65568

// edge kernel SMEM: H buffers (hi|lo) x2, reduction, control
#define B_H(b)    ((b) * 65536)            // HH at +0 (32KB), HL at +32768
#define B_RED     131072
#define B_TMEMPTR 133120
#define B_C2B     133128                   // 2 mbarriers
#define B_TOTAL   133152

// Prepared weights (transposed+packed for TMEM A-operand):
// word(m, c) = bf16(W[2c, m]) | bf16(W[2c+1, m])<<16  (hi and lo splits)
__device__ __align__(16) uint32_t g_W1at_h[8192];   // W1[0:128]^T  [m=128][c=64]
__device__ __align__(16) uint32_t g_W1at_l[8192];
__device__ __align__(16) uint32_t g_W1bt_h[8192];   // W1[128:256]^T
__device__ __align__(16) uint32_t g_W1bt_l[8192];
__device__ __align__(16) uint32_t g_W2t_h[8192];    // W2^T
__device__ __align__(16) uint32_t g_W2t_l[8192];

// Per-node layer-1 partials (fp32), written by node_kernel.
__device__ __align__(16) float g_y1[(size_t)MAXN * 128];
__device__ __align__(16) float g_y2[(size_t)MAXN * 128];

__device__ __forceinline__ int sw128(int off) { return off ^ ((off >> 3) & 0x70); }

#if EDGE_USE_TC

__device__ __forceinline__ uint32_t smem_u32_of(const void* p) {
    uint32_t a;
    asm("{ .reg .u64 t; cvta.to.shared.u64 t, %1; cvt.u32.u64 %0, t; }"
        : "=r"(a) : "l"(p));
    return a;
}
__device__ __forceinline__ uint32_t elect_one() {
    uint32_t pred;
    asm volatile("{ .reg .pred p; elect.sync _|p, 0xFFFFFFFF; selp.b32 %0, 1, 0, p; }"
                 : "=r"(pred));
    return pred;
}
__device__ __forceinline__ uint64_t smem_desc(uint32_t addr) {
    // SW128, Blackwell version=1, SBO=64, LBO=1 (K-major)
    return 0x4000404000010000ULL | ((uint64_t)(addr >> 4) & 0x3FFF);
}
__device__ __forceinline__ void mma_f16_ts(uint32_t d_tmem, uint32_t a_tmem,
                                           uint64_t b_desc, uint32_t en) {
    asm volatile(
        "{\n\t.reg .pred p;\n\tsetp.ne.u32 p, %4, 0;\n\t"
        "tcgen05.mma.cta_group::1.kind::f16 [%0], [%1], %2, %3, {%5,%5,%5,%5}, p;\n\t}"
        :: "r"(d_tmem), "r"(a_tmem), "l"(b_desc), "r"(IDESC), "r"(en), "r"(0u)
        : "memory");
}

#define TCGEN05_ALLOC(sa, n) \
    asm volatile("tcgen05.alloc.cta_group::1.sync.aligned.shared::cta.b32 [%0], %1;" \
                 :: "r"((uint32_t)(sa)), "r"((uint32_t)(n)) : "memory")
#define TCGEN05_DEALLOC(t, n) \
    asm volatile("tcgen05.dealloc.cta_group::1.sync.aligned.b32 %0, %1;" \
                 :: "r"(t), "r"((uint32_t)(n)))
#define TCGEN05_COMMIT(mb) \
    asm volatile("tcgen05.commit.cta_group::1.mbarrier::arrive::one.shared::cluster.b64 [%0];" \
                 :: "r"((uint32_t)(mb)) : "memory")
#define TCGEN05_WAIT_LD()  asm volatile("tcgen05.wait::ld.sync.aligned;" ::: "memory")
#define TCGEN05_WAIT_ST()  asm volatile("tcgen05.wait::st.sync.aligned;" ::: "memory")
#define TCGEN05_FENCE_BEFORE() asm volatile("tcgen05.fence::before_thread_sync;" ::: "memory")
#define TCGEN05_FENCE_AFTER()  asm volatile("tcgen05.fence::after_thread_sync;" ::: "memory")
#define FENCE_ASYNC() asm volatile("fence.proxy.async.shared::cta;" ::: "memory")
#define MBARRIER_INIT(mb, c) \
    asm volatile("mbarrier.init.shared.b64 [%0], %1;" :: "r"((uint32_t)(mb)), "r"((uint32_t)(c)) : "memory")
#define MBARRIER_INVAL(mb) \
    asm volatile("mbarrier.inval.shared.b64 [%0];" :: "r"((uint32_t)(mb)) : "memory")

#define MBARRIER_WAIT_PARITY(mb, ph) do {                                          \
    uint32_t _m = (uint32_t)(mb), _p = (uint32_t)(ph), _done;                      \
    asm volatile("{\n\t.reg .pred p;\n\t"                                          \
        "mbarrier.try_wait.parity.acquire.cta.shared::cta.b64 p, [%1], %2;\n\t"    \
        "selp.b32 %0, 1, 0, p;\n\t}" : "=r"(_done) : "r"(_m), "r"(_p) : "memory"); \
    if (!_done) {                                                                  \
        asm volatile("{\n\t.reg .pred P1;\n\t"                                     \
        "WL_%=:\n\t"                                                               \
        "mbarrier.try_wait.parity.acquire.cta.shared::cta.b64 P1, [%0], %1, 0x989680;\n\t" \
        "@P1 bra.uni WD_%=;\n\t"                                                   \
        "bra.uni WL_%=;\n\t"                                                       \
        "WD_%=:\n\t}" :: "r"(_m), "r"(_p) : "memory");                             \
    }                                                                              \
} while (0)

#define LDTM_X32(r, a)                                                             \
    asm volatile("tcgen05.ld.sync.aligned.32x32b.x32.b32 "                         \
        "{%0,%1,%2,%3,%4,%5,%6,%7,%8,%9,%10,%11,%12,%13,%14,%15,"                  \
        "%16,%17,%18,%19,%20,%21,%22,%23,%24,%25,%26,%27,%28,%29,%30,%31}, [%32];" \
        : "=r"((r)[0]),"=r"((r)[1]),"=r"((r)[2]),"=r"((r)[3]),                     \
          "=r"((r)[4]),"=r"((r)[5]),"=r"((r)[6]),"=r"((r)[7]),                     \
          "=r"((r)[8]),"=r"((r)[9]),"=r"((r)[10]),"=r"((r)[11]),                   \
          "=r"((r)[12]),"=r"((r)[13]),"=r"((r)[14]),"=r"((r)[15]),                 \
          "=r"((r)[16]),"=r"((r)[17]),"=r"((r)[18]),"=r"((r)[19]),                 \
          "=r"((r)[20]),"=r"((r)[21]),"=r"((r)[22]),"=r"((r)[23]),                 \
          "=r"((r)[24]),"=r"((r)[25]),"=r"((r)[26]),"=r"((r)[27]),                 \
          "=r"((r)[28]),"=r"((r)[29]),"=r"((r)[30]),"=r"((r)[31])                  \
        : "r"(a))

#define STTM_X32(a, r)                                                             \
    asm volatile("tcgen05.st.sync.aligned.32x32b.x32.b32 [%0], "                   \
        "{%1,%2,%3,%4,%5,%6,%7,%8,%9,%10,%11,%12,%13,%14,%15,%16,"                 \
        "%17,%18,%19,%20,%21,%22,%23,%24,%25,%26,%27,%28,%29,%30,%31,%32};"        \
        :: "r"(a),                                                                 \
           "r"((r)[0]),"r"((r)[1]),"r"((r)[2]),"r"((r)[3]),                        \
           "r"((r)[4]),"r"((r)[5]),"r"((r)[6]),"r"((r)[7]),                        \
           "r"((r)[8]),"r"((r)[9]),"r"((r)[10]),"r"((r)[11]),                      \
           "r"((r)[12]),"r"((r)[13]),"r"((r)[14]),"r"((r)[15]),                    \
           "r"((r)[16]),"r"((r)[17]),"r"((r)[18]),"r"((r)[19]),                    \
           "r"((r)[20]),"r"((r)[21]),"r"((r)[22]),"r"((r)[23]),                    \
           "r"((r)[24]),"r"((r)[25]),"r"((r)[26]),"r"((r)[27]),                    \
           "r"((r)[28]),"r"((r)[29]),"r"((r)[30]),"r"((r)[31])                     \
        : "memory")

__device__ __forceinline__ uint32_t pack_bf2f(float a, float b) {
    __nv_bfloat162 t = __floats2bfloat162_rn(a, b);   // .x = low half
    return *reinterpret_cast<uint32_t*>(&t);
}

#endif  // EDGE_USE_TC

// ------------------------------ prep kernel -------------------------------
__global__ void prep_kernel(const float* __restrict__ W1,
                            const float* __restrict__ W2) {
    int i = blockIdx.x * blockDim.x + threadIdx.x;
    const float* src = nullptr;
    uint32_t *dh = nullptr, *dl = nullptr;
    int j = i, kofs = 0;
    if (i < 8192)       { src = W1; dh = g_W1at_h; dl = g_W1at_l; kofs = 0;   }
    else if (i < 16384) { src = W1; dh = g_W1bt_h; dl = g_W1bt_l; kofs = 128; j = i - 8192;  }
    else if (i < 24576) { src = W2; dh = g_W2t_h;  dl = g_W2t_l;  kofs = 0;   j = i - 16384; }
    else return;
    int m = j >> 6, c = j & 63;
    float a = src[(kofs + 2 * c) * 128 + m];
    float b = src[(kofs + 2 * c + 1) * 128 + m];
    __nv_bfloat16 ah = __float2bfloat16_rn(a), bh = __float2bfloat16_rn(b);
    float al = a - __bfloat162float(ah), bl = b - __bfloat162float(bh);
    __nv_bfloat162 hi; hi.x = ah; hi.y = bh;
    __nv_bfloat162 lo = __floats2bfloat162_rn(al, bl);
    dh[j] = *reinterpret_cast<uint32_t*>(&hi);
    dl[j] = *reinterpret_cast<uint32_t*>(&lo);
}

// --------------------------- node precompute kernel ------------------------
// y1 = x1 @ W1a, y2 = x2 @ W1b (fp32 out, 3-term bf16 split GEMM).
__global__ __launch_bounds__(NT, 1)
void node_kernel(const float* __restrict__ x1, const float* __restrict__ x2,
                 int N) {
#if EDGE_USE_TC
    extern __shared__ char smem[];
    const uint32_t sb = smem_u32_of(smem);
    const int tid  = threadIdx.x;
    const int lane = tid & 31;
    const int wid  = tid >> 5;
    const int sp   = wid & 3;
    const int cc   = wid >> 2;
    const uint32_t rowbits = (uint32_t)sp << 21;
    const int g    = sp * 32 + lane;

    if (wid == 0) TCGEN05_ALLOC(sb + A_TMEMPTR, 512);
    if (tid == 0) MBARRIER_INIT(sb + A_BAR, 1);
    __syncthreads();
    uint32_t tmem;
    asm volatile("ld.shared.b32 %0, [%1];" : "=r"(tmem) : "r"(sb + A_TMEMPTR));
    const uint32_t tD = tmem + 256;

    // upload W1a (cols 0-127) and W1b (cols 128-255)
    {
        uint32_t ww[32];
        if (wid < 4) {
#pragma unroll
            for (int q = 0; q < 2; ++q) {
#pragma unroll
                for (int i = 0; i < 32; ++i) ww[i] = g_W1at_h[g * 64 + 32 * q + i];
                STTM_X32(tmem + 32 * q + rowbits, ww);
            }
#pragma unroll
            for (int q = 0; q < 2; ++q) {
#pragma unroll
                for (int i = 0; i < 32; ++i) ww[i] = g_W1at_l[g * 64 + 32 * q + i];
                STTM_X32(tmem + 64 + 32 * q + rowbits, ww);
            }
            TCGEN05_WAIT_ST();
        } else if (wid < 8) {
#pragma unroll
            for (int q = 0; q < 2; ++q) {
#pragma unroll
                for (int i = 0; i < 32; ++i) ww[i] = g_W1bt_h[g * 64 + 32 * q + i];
                STTM_X32(tmem + 128 + 32 * q + rowbits, ww);
            }
#pragma unroll
            for (int q = 0; q < 2; ++q) {
#pragma unroll
                for (int i = 0; i < 32; ++i) ww[i] = g_W1bt_l[g * 64 + 32 * q + i];
                STTM_X32(tmem + 192 + 32 * q + rowbits, ww);
            }
            TCGEN05_WAIT_ST();
        }
    }
    TCGEN05_FENCE_BEFORE();
    __syncthreads();

    const int nt1 = (N + 127) / 128;
    const int total = 2 * nt1;
    const int coff = 8 * (lane & 15);
    const int csel = lane >> 4;
    int ph = 0;

    for (int tt = blockIdx.x; tt < total; tt += GRID) {
        const int mt = (tt >= nt1);
        const int tile = mt ? tt - nt1 : tt;
        const float* xb = mt ? x2 : x1;
        float* yb = mt ? g_y2 : g_y1;
        const uint32_t aT = tmem + (mt ? 128u : 0u);

        // load 8 rows per warp, split to PH/PL (SW128 K-major)
#pragma unroll
        for (int i = 0; i < 8; ++i) {
            int r = wid * 8 + i;
            long long node = (long long)tile * 128 + r;
            float4 v = make_float4(0.f, 0.f, 0.f, 0.f);
            if (node < N)
                v = reinterpret_cast<const float4*>(xb + node * 128)[lane];
            __nv_bfloat162 h0 = __floats2bfloat162_rn(v.x, v.y);
            __nv_bfloat162 h1 = __floats2bfloat162_rn(v.z, v.w);
            uint2 hh = make_uint2(*reinterpret_cast<uint32_t*>(&h0),
                                  *reinterpret_cast<uint32_t*>(&h1));
            uint2 ll = make_uint2(pack_bf2f(v.x - __bfloat162float(h0.x),
                                            v.y - __bfloat162float(h0.y)),
                                  pack_bf2f(v.z - __bfloat162float(h1.x),
                                            v.w - __bfloat162float(h1.y)));
            int off = csel * 16384 + sw128(r * 128 + coff);
            *reinterpret_cast<uint2*>(smem + A_PH + off) = hh;
            *reinterpret_cast<uint2*>(smem + A_PL + off) = ll;
        }
        FENCE_ASYNC();
        __syncthreads();

        if (wid == 4 && elect_one()) {
            TCGEN05_FENCE_AFTER();
#pragma unroll
            for (int pass = 0; pass < 3; ++pass) {
                const uint32_t acol = (pass == 2) ? 64u : 0u;
                const uint32_t bbase = (pass == 1) ? A_PL : A_PH;
                for (int c = 0; c < 2; ++c) {
                    uint64_t bd = smem_desc(sb + bbase + c * 16384);
                    for (int k = 0; k < 4; ++k)
                        mma_f16_ts(tD, aT + acol + (c * 4 + k) * 8, bd + k * 2,
                                   (pass == 0 && c == 0 && k == 0) ? 0u : 1u);
                }
            }
            TCGEN05_COMMIT(sb + A_BAR);
        }
        MBARRIER_WAIT_PARITY(sb + A_BAR, ph); ph ^= 1;
        TCGEN05_FENCE_AFTER();

        uint32_t d[32];
        LDTM_X32(d, tD + 32 * cc);
        TCGEN05_WAIT_LD();
#pragma unroll
        for (int j = 0; j < 32; ++j) {
            long long node = (long long)tile * 128 + cc * 32 + j;
            if (node < N) yb[node * 128 + g] = __uint_as_float(d[j]);
        }
        // LDTM done before loop's next sync -> safe to overwrite P and D
    }

    __syncthreads();
    if (tid == 0) MBARRIER_INVAL(sb + A_BAR);
    __syncthreads();
    if (wid == 0) TCGEN05_DEALLOC(tmem, 512);
#else
    (void)x1; (void)x2; (void)N;
#endif
}

// ------------------------------ edge kernel --------------------------------
__global__ __launch_bounds__(NT, 1)
void edge_kernel(const int* __restrict__ ei,
                 const float* __restrict__ b1g,
                 const float* __restrict__ b2g,
                 const float* __restrict__ W3g,
                 const float* __restrict__ b3g,
                 float* __restrict__ out, int E) {
#if EDGE_USE_TC
    extern __shared__ char smem[];
    const uint32_t sb = smem_u32_of(smem);
    const int tid  = threadIdx.x;
    const int lane = tid & 31;
    const int wid  = tid >> 5;
    const int sp   = wid & 3;
    const int cc   = wid >> 2;
    const uint32_t rowbits = (uint32_t)sp << 21;
    const int g    = sp * 32 + lane;
    const int ntiles = (E + TILE_M - 1) / TILE_M;

    if (wid == 0) TCGEN05_ALLOC(sb + B_TMEMPTR, 512);
    if (tid == 0) { MBARRIER_INIT(sb + B_C2B, 1); MBARRIER_INIT(sb + B_C2B + 8, 1); }
    __syncthreads();
    uint32_t tmem;
    asm volatile("ld.shared.b32 %0, [%1];" : "=r"(tmem) : "r"(sb + B_TMEMPTR));

    // upload W2 (hi cols 0-63, lo cols 64-127)
    if (wid < 4) {
        uint32_t ww[32];
#pragma unroll
        for (int q = 0; q < 2; ++q) {
#pragma unroll
            for (int i = 0; i < 32; ++i) ww[i] = g_W2t_h[g * 64 + 32 * q + i];
            STTM_X32(tmem + 32 * q + rowbits, ww);
        }
#pragma unroll
        for (int q = 0; q < 2; ++q) {
#pragma unroll
            for (int i = 0; i < 32; ++i) ww[i] = g_W2t_l[g * 64 + 32 * q + i];
            STTM_X32(tmem + 64 + 32 * q + rowbits, ww);
        }
        TCGEN05_WAIT_ST();
    }
    TCGEN05_FENCE_BEFORE();
    __syncthreads();

    // per-lane constants
    const float4 b1v4 = reinterpret_cast<const float4*>(b1g)[lane]; // feats 4*lane..
    const float b2v = b2g[g];
    const float w3v = W3g[g];
    const float b3v = b3g[0];
    const int coff = 8 * (lane & 15);
    const int csel = lane >> 4;
    const int mbase = wid * 8;

    // gather+combine tile tt into H buffer b
    auto gather_combine = [&](int tt, int b) {
        int eidx = tt * TILE_M + mbase + (lane & 7);
        int nd = -1;
        if (lane < 16 && eidx < E)
            nd = ei[(lane >= 8 ? E : 0) + eidx];
#pragma unroll
        for (int half = 0; half < 2; ++half) {
            float4 va[4], vb[4];
#pragma unroll
            for (int i = 0; i < 4; ++i) {
                int ii = half * 4 + i;
                int s = __shfl_sync(0xffffffffu, nd, ii);
                int d = __shfl_sync(0xffffffffu, nd, 8 + ii);
                va[i] = (s >= 0)
                    ? reinterpret_cast<const float4*>(g_y1 + (long long)s * 128)[lane]
                    : make_float4(0.f, 0.f, 0.f, 0.f);
                vb[i] = (d >= 0)
                    ? reinterpret_cast<const float4*>(g_y2 + (long long)d * 128)[lane]
                    : make_float4(0.f, 0.f, 0.f, 0.f);
            }
#pragma unroll
            for (int i = 0; i < 4; ++i) {
                int m = mbase + half * 4 + i;
                float v0 = fmaxf(va[i].x + vb[i].x + b1v4.x, 0.f);
                float v1 = fmaxf(va[i].y + vb[i].y + b1v4.y, 0.f);
                float v2 = fmaxf(va[i].z + vb[i].z + b1v4.z, 0.f);
                float v3 = fmaxf(va[i].w + vb[i].w + b1v4.w, 0.f);
                __nv_bfloat162 h0 = __floats2bfloat162_rn(v0, v1);
                __nv_bfloat162 h1 = __floats2bfloat162_rn(v2, v3);
                uint2 hh = make_uint2(*reinterpret_cast<uint32_t*>(&h0),
                                      *reinterpret_cast<uint32_t*>(&h1));
                uint2 ll = make_uint2(pack_bf2f(v0 - __bfloat162float(h0.x),
                                                v1 - __bfloat162float(h0.y)),
                                      pack_bf2f(v2 - __bfloat162float(h1.x),
                                                v3 - __bfloat162float(h1.y)));
                int off = csel * 16384 + sw128(m * 128 + coff);
                *reinterpret_cast<uint2*>(smem + B_H(b) + off) = hh;
                *reinterpret_cast<uint2*>(smem + B_H(b) + 32768 + off) = ll;
            }
        }
        FENCE_ASYNC();
    };

    auto issue_chain2 = [&](int b) {
        TCGEN05_FENCE_AFTER();
        const uint32_t tD = tmem + 128 + 128 * (uint32_t)b;
#pragma unroll
        for (int pass = 0; pass < 3; ++pass) {
            const uint32_t acol = (pass == 2) ? 64u : 0u;
            const uint32_t bbase = B_H(b) + ((pass == 1) ? 32768u : 0u);
            for (int c = 0; c < 2; ++c) {
                uint64_t bd = smem_desc(sb + bbase + c * 16384);
                for (int k = 0; k < 4; ++k)
                    mma_f16_ts(tD, tmem + acol + (c * 4 + k) * 8, bd + k * 2,
                               (pass == 0 && c == 0 && k == 0) ? 0u : 1u);
            }
        }
        TCGEN05_COMMIT(sb + B_C2B + 8 * b);
    };

    auto epilogue = [&](int pt, int pb, int& phref) {
        MBARRIER_WAIT_PARITY(sb + B_C2B + 8 * pb, phref); phref ^= 1;
        TCGEN05_FENCE_AFTER();
        const uint32_t tD = tmem + 128 + 128 * (uint32_t)pb;
        uint32_t d2[32];
        LDTM_X32(d2, tD + 32 * cc);
        TCGEN05_WAIT_LD();
        float v[32];
#pragma unroll
        for (int j = 0; j < 32; ++j)
            v[j] = fmaxf(__uint_as_float(d2[j]) + b2v, 0.0f) * w3v;
#pragma unroll
        for (int m = 16; m > 0; m >>= 1) {
#pragma unroll
            for (int j = 0; j < m; ++j) {
                float x = (lane & m) ? v[j] : v[j + m];
                float y = __shfl_xor_sync(0xffffffffu, x, m);
                v[j] = ((lane & m) ? v[j + m] : v[j]) + y;
            }
        }
        ((float*)(smem + B_RED))[sp * 128 + cc * 32 + lane] = v[0];
        __syncthreads();
        if (tid < TILE_M) {
            int e = pt * TILE_M + tid;
            if (e < E) {
                const float* red = (const float*)(smem + B_RED);
                out[e] = red[tid] + red[128 + tid] + red[256 + tid] +
                         red[384 + tid] + b3v;
            }
        }
    };

    int ph2[2] = {0, 0};
    int iter = 0, pend_t = -1;
    for (int t = blockIdx.x; t < ntiles; t += GRID, ++iter) {
        const int b = iter & 1;
        gather_combine(t, b);
        __syncthreads();                       // H[b] ready; prev drains done
        if (wid == 4 && elect_one()) issue_chain2(b);
        if (pend_t >= 0) epilogue(pend_t, b ^ 1, ph2[b ^ 1]);
        pend_t = t;
    }
    if (pend_t >= 0) {
        const int pb = (iter - 1) & 1;
        epilogue(pend_t, pb, ph2[pb]);
    }

    __syncthreads();
    if (tid == 0) { MBARRIER_INVAL(sb + B_C2B); MBARRIER_INVAL(sb + B_C2B + 8); }
    __syncthreads();
    if (wid == 0) TCGEN05_DEALLOC(tmem, 512);
#else
    (void)ei; (void)b1g; (void)b2g; (void)W3g;
    int stride = gridDim.x * blockDim.x;
    for (int e = blockIdx.x * blockDim.x + threadIdx.x; e < E; e += stride)
        out[e] = b3g[0];
#endif
}

// Full-precision standalone fallback (launched only if tc kernels unavailable).
__global__ __launch_bounds__(256, 1)
void edge_mlp_ref_kernel(const float* __restrict__ x1,
                         const float* __restrict__ x2,
                         const int* __restrict__ ei,
                         const float* __restrict__ W1, const float* __restrict__ b1,
                         const float* __restrict__ W2, const float* __restrict__ b2,
                         const float* __restrict__ W3, const float* __restrict__ b3,
                         float* __restrict__ out, int E) {
    int stride = gridDim.x * blockDim.x;
    for (int e = blockIdx.x * blockDim.x + threadIdx.x; e < E; e += stride) {
        const float* xs = x1 + (long long)ei[e] * 128;
        const float* xt = x2 + (long long)ei[E + e] * 128;
        float h1[128], h2[128];
        for (int f = 0; f < 128; ++f) {
            float a = b1[f];
            for (int k = 0; k < 128; ++k) a += xs[k] * W1[k * 128 + f];
            for (int k = 0; k < 128; ++k) a += xt[k] * W1[(128 + k) * 128 + f];
            h1[f] = fmaxf(a, 0.0f);
        }
        for (int g2 = 0; g2 < 128; ++g2) {
            float a = b2[g2];
            for (int f = 0; f < 128; ++f) a += h1[f] * W2[f * 128 + g2];
            h2[g2] = fmaxf(a, 0.0f);
        }
        float acc = b3[0];
        for (int g2 = 0; g2 < 128; ++g2) acc += h2[g2] * W3[g2];
        out[e] = acc;
    }
}

extern "C" void kernel_launch(void* const* d_in, const int* in_sizes, int n_in,
                              void* d_out, int out_size) {
    const float* x1 = (const float*)d_in[0];
    const float* x2 = (const float*)d_in[1];
    const int*   ei = (const int*)d_in[2];
    const float* W1 = (const float*)d_in[3];
    const float* b1 = (const float*)d_in[4];
    const float* W2 = (const float*)d_in[5];
    const float* b2 = (const float*)d_in[6];
    const float* W3 = (const float*)d_in[7];
    const float* b3 = (const float*)d_in[8];
    float*       out = (float*)d_out;

    int E = in_sizes[2] / 2;
    int N = in_sizes[0] / 128;

    static int use_tc = -1;
    if (use_tc < 0) {
        cudaFuncAttributes attr;
        cudaError_t err = cudaFuncGetAttributes(&attr, edge_kernel);
        use_tc = (err == cudaSuccess && attr.maxThreadsPerBlock >= NT) ? 1 : 0;
        if (use_tc) {
            if (cudaFuncSetAttribute(node_kernel,
                                     cudaFuncAttributeMaxDynamicSharedMemorySize,
                                     A_TOTAL) != cudaSuccess) use_tc = 0;
            if (cudaFuncSetAttribute(edge_kernel,
                                     cudaFuncAttributeMaxDynamicSharedMemorySize,
                                     B_TOTAL) != cudaSuccess) use_tc = 0;
        }
        cudaGetLastError();  // clear probe state
    }

    if (use_tc && N <= MAXN) {
        prep_kernel<<<96, 256>>>(W1, W2);
        node_kernel<<<GRID, NT, A_TOTAL>>>(x1, x2, N);
        edge_kernel<<<GRID, NT, B_TOTAL>>>(ei, b1, b2, W3, b3, out, E);
    } else {
        edge_mlp_ref_kernel<<<GRID, 256>>>(x1, x2, ei, W1, b1, W2, b2, W3, b3,
                                           out, E);
    }
}